// round 16
// baseline (speedup 1.0000x reference)
#include <cuda_runtime.h>
#include <cuda_bf16.h>
#include <cstdint>

// Problem constants
#define BATCH 2
#define SEQ   2048
#define EMB   1024
#define NH    16
#define HD    64
#define FF    4096
#define NL    4
#define VOC   32000
#define BS    (BATCH*SEQ)   // 4096 rows

typedef __nv_bfloat16 bf16;

// ---------------- scratch (device globals; no allocation) ----------------
__device__ float g_h   [(size_t)BS * EMB];
__device__ float g_tmp [(size_t)BS * EMB];

__device__ bf16 g_ahi [(size_t)BS * EMB];      // h split (gemm A input)
__device__ bf16 g_alo [(size_t)BS * EMB];
__device__ bf16 g_ffh [(size_t)BS * FF];       // FF hidden split
__device__ bf16 g_ffl [(size_t)BS * FF];
__device__ bf16 g_qkvh[(size_t)BS * 3 * EMB];  // qkv split
__device__ bf16 g_qkvl[(size_t)BS * 3 * EMB];
__device__ bf16 g_ath [(size_t)BS * EMB];      // attention out split
__device__ bf16 g_atl [(size_t)BS * EMB];

__device__ bf16 g_wkqv_hi[(size_t)NL * 3 * EMB * EMB];
__device__ bf16 g_wkqv_lo[(size_t)NL * 3 * EMB * EMB];
__device__ bf16 g_wo_hi  [(size_t)NL * EMB * EMB];
__device__ bf16 g_wo_lo  [(size_t)NL * EMB * EMB];
__device__ bf16 g_wup_hi [(size_t)NL * EMB * FF];
__device__ bf16 g_wup_lo [(size_t)NL * EMB * FF];
__device__ bf16 g_wdn_hi [(size_t)NL * FF * EMB];
__device__ bf16 g_wdn_lo [(size_t)NL * FF * EMB];
__device__ bf16 g_we_hi  [(size_t)VOC * EMB];
__device__ bf16 g_we_lo  [(size_t)VOC * EMB];

// ==================== PTX helpers (baseline ISA only) ====================
__device__ __forceinline__ uint32_t cvta_smem(const void* p) {
    uint32_t a;
    asm("{ .reg .u64 t; cvta.to.shared.u64 t, %1; cvt.u32.u64 %0, t; }"
        : "=r"(a) : "l"(p));
    return a;
}
__device__ __forceinline__ void cp_async16(uint32_t dst, const void* src) {
    asm volatile("cp.async.cg.shared.global [%0], [%1], 16;" :: "r"(dst), "l"(src));
}
__device__ __forceinline__ void cp_commit() {
    asm volatile("cp.async.commit_group;" ::: "memory");
}
__device__ __forceinline__ void cp_wait1() {
    asm volatile("cp.async.wait_group 1;" ::: "memory");
}
__device__ __forceinline__ void cp_wait0() {
    asm volatile("cp.async.wait_group 0;" ::: "memory");
}
__device__ __forceinline__ void ldmatrix_x4(uint32_t* r, uint32_t addr) {
    asm volatile("ldmatrix.sync.aligned.m8n8.x4.shared.b16 {%0,%1,%2,%3}, [%4];"
                 : "=r"(r[0]), "=r"(r[1]), "=r"(r[2]), "=r"(r[3]) : "r"(addr));
}
__device__ __forceinline__ void ldmatrix_x4_t(uint32_t* r, uint32_t addr) {
    asm volatile("ldmatrix.sync.aligned.m8n8.x4.trans.shared.b16 {%0,%1,%2,%3}, [%4];"
                 : "=r"(r[0]), "=r"(r[1]), "=r"(r[2]), "=r"(r[3]) : "r"(addr));
}
__device__ __forceinline__ void mma_bf16(float* c, const uint32_t* a, const uint32_t* b) {
    asm volatile(
        "mma.sync.aligned.m16n8k16.row.col.f32.bf16.bf16.f32 "
        "{%0,%1,%2,%3}, {%4,%5,%6,%7}, {%8,%9}, {%0,%1,%2,%3};"
        : "+f"(c[0]), "+f"(c[1]), "+f"(c[2]), "+f"(c[3])
        : "r"(a[0]), "r"(a[1]), "r"(a[2]), "r"(a[3]), "r"(b[0]), "r"(b[1]));
}
__device__ __forceinline__ void sts32(uint32_t addr, uint32_t v) {
    asm volatile("st.shared.b32 [%0], %1;" :: "r"(addr), "r"(v) : "memory");
}
__device__ __forceinline__ void split_pack(float a, float b, uint32_t& hi, uint32_t& lo) {
    bf16 ha = __float2bfloat16(a), hb = __float2bfloat16(b);
    bf16 la = __float2bfloat16(a - __bfloat162float(ha));
    bf16 lb = __float2bfloat16(b - __bfloat162float(hb));
    __nv_bfloat162 H; H.x = ha; H.y = hb;
    __nv_bfloat162 L; L.x = la; L.y = lb;
    hi = *(uint32_t*)&H; lo = *(uint32_t*)&L;
}

// ==================== weight conversion kernels ====================
__global__ void __launch_bounds__(256) cvt_kernel(
    const float* __restrict__ in, bf16* __restrict__ hi,
    bf16* __restrict__ lo, size_t n4)
{
    size_t i = (size_t)blockIdx.x * 256 + threadIdx.x;
    if (i >= n4) return;
    float4 v = ((const float4*)in)[i];
    uint32_t h0, l0, h1, l1;
    split_pack(v.x, v.y, h0, l0);
    split_pack(v.z, v.w, h1, l1);
    ((uint32_t*)hi)[2 * i]     = h0;
    ((uint32_t*)hi)[2 * i + 1] = h1;
    ((uint32_t*)lo)[2 * i]     = l0;
    ((uint32_t*)lo)[2 * i + 1] = l1;
}

// fp32 [R][C] -> bf16 hi/lo transposed [C][R]
__global__ void __launch_bounds__(256) cvt_t_kernel(
    const float* __restrict__ in, bf16* __restrict__ hi,
    bf16* __restrict__ lo, int R, int C)
{
    __shared__ float t[32][33];
    const int c0 = blockIdx.x * 32, r0 = blockIdx.y * 32;
    const int tx = threadIdx.x, ty = threadIdx.y;   // 32 x 8
#pragma unroll
    for (int j = 0; j < 32; j += 8)
        t[ty + j][tx] = in[(size_t)(r0 + ty + j) * C + c0 + tx];
    __syncthreads();
#pragma unroll
    for (int j = 0; j < 32; j += 8) {
        float a = t[tx][ty + j];
        bf16 h = __float2bfloat16(a);
        bf16 l = __float2bfloat16(a - __bfloat162float(h));
        size_t o = (size_t)(c0 + ty + j) * R + r0 + tx;
        hi[o] = h; lo[o] = l;
    }
}

// ==================== HMMA bf16 split-3 GEMM, 128x128 tile ====================
// C = A(MxK) @ B(NxK)^T. 8 warps (4M x 2N), warp tile 32x64. K-chunk 64.
// Stage (64K): Ahi[0,16K) Alo[16K,32K) Bhi[32K,48K) Blo[48K,64K)
#define GBM 128
#define GBN 128
#define GBK 64
#define STG 65536
#define GEMM_SMEM (2 * STG)

__device__ __forceinline__ void hgemm_prefetch(
    const bf16* Ahi, const bf16* Alo, const bf16* Bhi, const bf16* Blo,
    int K, int m0, int n0, int tid, int k0, uint32_t st)
{
    const int r  = tid >> 1;
    const int s0 = (tid & 1) * 4;
    const bf16* pAh = Ahi + (size_t)(m0 + r) * K + k0;
    const bf16* pAl = Alo + (size_t)(m0 + r) * K + k0;
    const bf16* pBh = Bhi + (size_t)(n0 + r) * K + k0;
    const bf16* pBl = Blo + (size_t)(n0 + r) * K + k0;
#pragma unroll
    for (int j = 0; j < 4; j++) {
        int s = s0 + j;
        uint32_t off = r * 128 + ((s * 16) ^ ((r & 7) << 4));
        cp_async16(st + off,         pAh + s * 8);
        cp_async16(st + 16384 + off, pAl + s * 8);
        cp_async16(st + 32768 + off, pBh + s * 8);
        cp_async16(st + 49152 + off, pBl + s * 8);
    }
}

template<bool BIAS, bool RELU, bool OUTBF>
__global__ void __launch_bounds__(256, 1) hgemm_kernel(
    const bf16* __restrict__ Ahi, const bf16* __restrict__ Alo,
    const bf16* __restrict__ Bhi, const bf16* __restrict__ Blo,
    const float* __restrict__ bias, float* __restrict__ C,
    bf16* __restrict__ Chi, bf16* __restrict__ Clo,
    int M, int N, int K)
{
    extern __shared__ char sm[];
    const int tid = threadIdx.x;
    const int lane = tid & 31;
    const int warp = tid >> 5;
    const int warpM = warp & 3;          // 0..3 (x32 rows)
    const int warpN = warp >> 2;         // 0..1 (x64 cols)
    const int m0 = blockIdx.y * GBM;
    const int n0 = blockIdx.x * GBN;
    const uint32_t sbase = cvta_smem(sm);

    float acc[2][8][4];
#pragma unroll
    for (int i = 0; i < 2; i++)
#pragma unroll
        for (int j = 0; j < 8; j++)
#pragma unroll
            for (int k = 0; k < 4; k++) acc[i][j][k] = 0.f;

    const int nch = K / GBK;

    hgemm_prefetch(Ahi, Alo, Bhi, Blo, K, m0, n0, tid, 0, sbase);
    cp_commit();

    const int a_row_b = warpM * 32 + (lane & 7) + ((lane >> 3) & 1) * 8;
    const int a_col_b = ((lane >> 4) & 1) * 16;
    const int b_row_b = warpN * 64 + (lane & 7) + ((lane >> 4) & 1) * 8;
    const int b_col_b = ((lane >> 3) & 1) * 16;

    for (int i = 0; i < nch; i++) {
        const int s = i & 1;
        if (i + 1 < nch) {
            hgemm_prefetch(Ahi, Alo, Bhi, Blo, K, m0, n0, tid,
                           (i + 1) * GBK, sbase + (s ^ 1) * STG);
            cp_commit();
            cp_wait1();
        } else {
            cp_wait0();
        }
        __syncthreads();

        const uint32_t st = sbase + s * STG;
#pragma unroll
        for (int kk = 0; kk < 4; kk++) {
            uint32_t ah[2][4], al[2][4];
#pragma unroll
            for (int mt = 0; mt < 2; mt++) {
                int row = a_row_b + mt * 16;
                int col = kk * 32 + a_col_b;
                uint32_t addr = st + row * 128 + (col ^ ((row & 7) << 4));
                ldmatrix_x4(ah[mt], addr);
                ldmatrix_x4(al[mt], addr + 16384);
            }
            uint32_t bh[8][2], bl[8][2];
#pragma unroll
            for (int nt2 = 0; nt2 < 4; nt2++) {
                int row = b_row_b + nt2 * 16;
                int col = kk * 32 + b_col_b;
                uint32_t addr = st + 32768 + row * 128 + (col ^ ((row & 7) << 4));
                uint32_t r[4];
                ldmatrix_x4(r, addr);
                bh[nt2 * 2][0] = r[0]; bh[nt2 * 2][1] = r[1];
                bh[nt2 * 2 + 1][0] = r[2]; bh[nt2 * 2 + 1][1] = r[3];
                ldmatrix_x4(r, addr + 16384);
                bl[nt2 * 2][0] = r[0]; bl[nt2 * 2][1] = r[1];
                bl[nt2 * 2 + 1][0] = r[2]; bl[nt2 * 2 + 1][1] = r[3];
            }
#pragma unroll
            for (int mt = 0; mt < 2; mt++)
#pragma unroll
                for (int nt = 0; nt < 8; nt++) mma_bf16(acc[mt][nt], ah[mt], bh[nt]);
#pragma unroll
            for (int mt = 0; mt < 2; mt++)
#pragma unroll
                for (int nt = 0; nt < 8; nt++) mma_bf16(acc[mt][nt], ah[mt], bl[nt]);
#pragma unroll
            for (int mt = 0; mt < 2; mt++)
#pragma unroll
                for (int nt = 0; nt < 8; nt++) mma_bf16(acc[mt][nt], al[mt], bh[nt]);
        }
        __syncthreads();
    }

    // ---- epilogue ----
    const int er = lane >> 2;
    const int ec = (lane & 3) * 2;
#pragma unroll
    for (int mt = 0; mt < 2; mt++) {
#pragma unroll
        for (int nt = 0; nt < 8; nt++) {
            int col = n0 + warpN * 64 + nt * 8 + ec;
            float bx = 0.f, by = 0.f;
            if (BIAS) { bx = bias[col]; by = bias[col + 1]; }
            int row0 = m0 + warpM * 32 + mt * 16 + er;
            float2 v0 = { acc[mt][nt][0] + bx, acc[mt][nt][1] + by };
            float2 v1 = { acc[mt][nt][2] + bx, acc[mt][nt][3] + by };
            if (RELU) {
                v0.x = fmaxf(v0.x, 0.f); v0.y = fmaxf(v0.y, 0.f);
                v1.x = fmaxf(v1.x, 0.f); v1.y = fmaxf(v1.y, 0.f);
            }
            if (OUTBF) {
                uint32_t h0, l0, h1, l1;
                split_pack(v0.x, v0.y, h0, l0);
                split_pack(v1.x, v1.y, h1, l1);
                size_t o0 = (size_t)row0 * N + col;
                size_t o1 = (size_t)(row0 + 8) * N + col;
                *(uint32_t*)(Chi + o0) = h0; *(uint32_t*)(Clo + o0) = l0;
                *(uint32_t*)(Chi + o1) = h1; *(uint32_t*)(Clo + o1) = l1;
            } else {
                *(float2*)(C + (size_t)row0 * N + col)       = v0;
                *(float2*)(C + (size_t)(row0 + 8) * N + col) = v1;
            }
        }
    }
}

// ==================== tensor-core flash attention (R15-proven core) ====================
// Output fused to bf16 hi/lo split.
#define FA_SMEM 98304

__global__ void __launch_bounds__(128, 2) flash_mma_kernel(
    const bf16* __restrict__ qh_g, const bf16* __restrict__ ql_g,
    bf16* __restrict__ oh_g, bf16* __restrict__ ol_g)
{
    extern __shared__ char sm[];
    const uint32_t sb = cvta_smem(sm);
    const int tid = threadIdx.x;
    const int lane = tid & 31;
    const int w = tid >> 5;
    const int qt = gridDim.x - 1 - blockIdx.x;   // longest first
    const int h = blockIdx.y;
    const int b = blockIdx.z;

    const uint32_t QH = sb, QL = sb + 8192;
    const uint32_t ST0 = sb + 16384;              // stage stride 32768
    const uint32_t PH = sb + 81920;               // PL = PH + 8192

    const size_t rowbase = (size_t)b * SEQ * (3 * EMB);
    const int hoff = h * (3 * HD);

    // ---- Q tile load (hi/lo) ----
    {
        const int r = tid >> 1;
        const int s0 = (tid & 1) * 4;
        const bf16* srcH = qh_g + rowbase + (size_t)(qt * 64 + r) * (3 * EMB) + hoff + HD;
        const bf16* srcL = ql_g + rowbase + (size_t)(qt * 64 + r) * (3 * EMB) + hoff + HD;
#pragma unroll
        for (int j = 0; j < 4; j++) {
            uint32_t o = r * 128 + (((s0 + j) * 16) ^ ((r & 7) << 4));
            cp_async16(QH + o, srcH + (s0 + j) * 8);
            cp_async16(QL + o, srcL + (s0 + j) * 8);
        }
    }
    cp_commit();

    const int pr = tid >> 1;
    const int ps0 = (tid & 1) * 4;
    const uint32_t prow = pr * 128;

#define PREFETCH_KV(kt_, stg_) do {                                              \
    const bf16* bH = qh_g + rowbase + (size_t)((kt_) * 64 + pr) * (3 * EMB) + hoff; \
    const bf16* bL = ql_g + rowbase + (size_t)((kt_) * 64 + pr) * (3 * EMB) + hoff; \
    _Pragma("unroll")                                                            \
    for (int j = 0; j < 4; j++) {                                                \
        uint32_t o = prow + (((ps0 + j) * 16) ^ ((pr & 7) << 4));                \
        cp_async16((stg_) + o,         bH + (ps0 + j) * 8);                      \
        cp_async16((stg_) + 8192 + o,  bL + (ps0 + j) * 8);                      \
        cp_async16((stg_) + 16384 + o, bH + 128 + (ps0 + j) * 8);                \
        cp_async16((stg_) + 24576 + o, bL + 128 + (ps0 + j) * 8);                \
    } } while (0)

    PREFETCH_KV(0, ST0);
    cp_commit();

    const int row_a = w * 16 + (lane & 15);
    const uint32_t colg_a = ((lane >> 4) & 1) * 16;
    const int row_kb = (lane & 7) + ((lane >> 4) & 1) * 8;
    const uint32_t col_kb = ((lane >> 3) & 1) * 16;
    const int row_v = (lane & 7) + ((lane >> 3) & 1) * 8;
    const uint32_t col_v = ((lane >> 4) & 1) * 16;

    const int er = lane >> 2, ec = (lane & 3) * 2;
    const int q0 = qt * 64 + w * 16 + er;

    float o_[8][4];
#pragma unroll
    for (int i = 0; i < 8; i++)
#pragma unroll
        for (int j = 0; j < 4; j++) o_[i][j] = 0.f;
    float m0 = -1e30f, m1 = -1e30f, l0 = 0.f, l1 = 0.f;

    const int nkt = qt + 1;
    for (int kt = 0; kt < nkt; kt++) {
        const uint32_t stg = ST0 + (kt & 1) * 32768;
        if (kt + 1 < nkt) {
            PREFETCH_KV(kt + 1, ST0 + ((kt + 1) & 1) * 32768);
            cp_commit();
            cp_wait1();
        } else {
            cp_wait0();
        }
        __syncthreads();

        float sa[8][4];
#pragma unroll
        for (int i = 0; i < 8; i++)
#pragma unroll
            for (int j = 0; j < 4; j++) sa[i][j] = 0.f;
#pragma unroll
        for (int kk = 0; kk < 4; kk++) {
            uint32_t aaddr = QH + row_a * 128 + ((kk * 32 + colg_a) ^ ((row_a & 7) << 4));
            uint32_t qh[4], ql[4];
            ldmatrix_x4(qh, aaddr);
            ldmatrix_x4(ql, aaddr + 8192);
#pragma unroll
            for (int ntp = 0; ntp < 4; ntp++) {
                int rb = ntp * 16 + row_kb;
                uint32_t baddr = stg + rb * 128 + ((kk * 32 + col_kb) ^ ((rb & 7) << 4));
                uint32_t kh[4], kl[4];
                ldmatrix_x4(kh, baddr);
                ldmatrix_x4(kl, baddr + 8192);
                mma_bf16(sa[2 * ntp],     qh, kh);
                mma_bf16(sa[2 * ntp + 1], qh, kh + 2);
                mma_bf16(sa[2 * ntp],     qh, kl);
                mma_bf16(sa[2 * ntp + 1], qh, kl + 2);
                mma_bf16(sa[2 * ntp],     ql, kh);
                mma_bf16(sa[2 * ntp + 1], ql, kh + 2);
            }
        }

        const bool diag = (kt == qt);
        float rm0 = -1e30f, rm1 = -1e30f;
#pragma unroll
        for (int nt = 0; nt < 8; nt++) {
#pragma unroll
            for (int c = 0; c < 4; c++) sa[nt][c] *= 0.125f;
            if (diag) {
                int kc = kt * 64 + nt * 8 + ec;
                if (kc     > q0)     sa[nt][0] = -1e30f;
                if (kc + 1 > q0)     sa[nt][1] = -1e30f;
                if (kc     > q0 + 8) sa[nt][2] = -1e30f;
                if (kc + 1 > q0 + 8) sa[nt][3] = -1e30f;
            }
            rm0 = fmaxf(rm0, fmaxf(sa[nt][0], sa[nt][1]));
            rm1 = fmaxf(rm1, fmaxf(sa[nt][2], sa[nt][3]));
        }
        rm0 = fmaxf(rm0, __shfl_xor_sync(0xffffffffu, rm0, 1));
        rm0 = fmaxf(rm0, __shfl_xor_sync(0xffffffffu, rm0, 2));
        rm1 = fmaxf(rm1, __shfl_xor_sync(0xffffffffu, rm1, 1));
        rm1 = fmaxf(rm1, __shfl_xor_sync(0xffffffffu, rm1, 2));
        const float mn0 = fmaxf(m0, rm0), mn1 = fmaxf(m1, rm1);
        const float cr0 = __expf(m0 - mn0), cr1 = __expf(m1 - mn1);
        m0 = mn0; m1 = mn1;
        float sum0 = 0.f, sum1 = 0.f;
        const int rA = w * 16 + er;
        const uint32_t rAoff = rA * 128, rBoff = (rA + 8) * 128;
        const uint32_t xsw = (uint32_t)((rA & 7) << 4);
#pragma unroll
        for (int nt = 0; nt < 8; nt++) {
            float p0 = __expf(sa[nt][0] - mn0);
            float p1 = __expf(sa[nt][1] - mn0);
            float p2 = __expf(sa[nt][2] - mn1);
            float p3 = __expf(sa[nt][3] - mn1);
            sum0 += p0 + p1; sum1 += p2 + p3;
            uint32_t hA, lA, hB, lB;
            split_pack(p0, p1, hA, lA);
            split_pack(p2, p3, hB, lB);
            uint32_t cb = (uint32_t)(nt * 16 + ec * 2) ^ xsw;
            sts32(PH + rAoff + cb, hA);
            sts32(PH + 8192 + rAoff + cb, lA);
            sts32(PH + rBoff + cb, hB);
            sts32(PH + 8192 + rBoff + cb, lB);
        }
        sum0 += __shfl_xor_sync(0xffffffffu, sum0, 1);
        sum0 += __shfl_xor_sync(0xffffffffu, sum0, 2);
        sum1 += __shfl_xor_sync(0xffffffffu, sum1, 1);
        sum1 += __shfl_xor_sync(0xffffffffu, sum1, 2);
        l0 = l0 * cr0 + sum0;
        l1 = l1 * cr1 + sum1;
#pragma unroll
        for (int nt = 0; nt < 8; nt++) {
            o_[nt][0] *= cr0; o_[nt][1] *= cr0;
            o_[nt][2] *= cr1; o_[nt][3] *= cr1;
        }
        __syncwarp();

#pragma unroll
        for (int kk2 = 0; kk2 < 4; kk2++) {
            uint32_t paddr = PH + row_a * 128 + ((kk2 * 32 + colg_a) ^ ((row_a & 7) << 4));
            uint32_t ph[4], pl[4];
            ldmatrix_x4(ph, paddr);
            ldmatrix_x4(pl, paddr + 8192);
#pragma unroll
            for (int ntp = 0; ntp < 4; ntp++) {
                int rv = kk2 * 16 + row_v;
                uint32_t vaddr = stg + 16384 + rv * 128 + ((ntp * 32 + col_v) ^ ((rv & 7) << 4));
                uint32_t vh[4], vl[4];
                ldmatrix_x4_t(vh, vaddr);
                ldmatrix_x4_t(vl, vaddr + 8192);
                mma_bf16(o_[2 * ntp],     ph, vh);
                mma_bf16(o_[2 * ntp + 1], ph, vh + 2);
                mma_bf16(o_[2 * ntp],     ph, vl);
                mma_bf16(o_[2 * ntp + 1], ph, vl + 2);
                mma_bf16(o_[2 * ntp],     pl, vh);
                mma_bf16(o_[2 * ntp + 1], pl, vh + 2);
            }
        }
        __syncthreads();
    }

    // ---- epilogue: write hi/lo bf16 split of O ----
    const float i0 = 1.f / l0, i1 = 1.f / l1;
    const size_t base0 = (size_t)(b * SEQ + q0) * EMB + h * HD;
    const size_t base1 = base0 + (size_t)8 * EMB;
#pragma unroll
    for (int nt = 0; nt < 8; nt++) {
        uint32_t h0, l0v, h1, l1v;
        split_pack(o_[nt][0] * i0, o_[nt][1] * i0, h0, l0v);
        split_pack(o_[nt][2] * i1, o_[nt][3] * i1, h1, l1v);
        *(uint32_t*)(oh_g + base0 + nt * 8 + ec) = h0;
        *(uint32_t*)(ol_g + base0 + nt * 8 + ec) = l0v;
        *(uint32_t*)(oh_g + base1 + nt * 8 + ec) = h1;
        *(uint32_t*)(ol_g + base1 + nt * 8 + ec) = l1v;
    }
#undef PREFETCH_KV
}

// ==================== embed (writes fp32 h + hi/lo split) ====================
__global__ void __launch_bounds__(256) embed_kernel(
    const int* __restrict__ x, const float* __restrict__ we,
    const float* __restrict__ pe, float* __restrict__ h,
    bf16* __restrict__ ah, bf16* __restrict__ al)
{
    int row = blockIdx.x;
    int s   = row % SEQ;
    int tok = x[row];
    int c = threadIdx.x * 4;
    float4 a = *(const float4*)(we + (size_t)tok * EMB + c);
    float4 b = *(const float4*)(pe + (size_t)s   * EMB + c);
    float4 o; o.x = a.x + b.x; o.y = a.y + b.y; o.z = a.z + b.z; o.w = a.w + b.w;
    size_t off = (size_t)row * EMB + c;
    *(float4*)(h + off) = o;
    uint32_t h0, l0, h1, l1;
    split_pack(o.x, o.y, h0, l0);
    split_pack(o.z, o.w, h1, l1);
    *(uint32_t*)(ah + off) = h0; *(uint32_t*)(ah + off + 2) = h1;
    *(uint32_t*)(al + off) = l0; *(uint32_t*)(al + off + 2) = l1;
}

// ==================== fused LayerNorm + residual (+ hi/lo split out) ====================
__global__ void __launch_bounds__(256) ln_add_kernel(
    const float* __restrict__ x, const float* __restrict__ gam,
    const float* __restrict__ bet, float* __restrict__ h,
    bf16* __restrict__ ah, bf16* __restrict__ al)
{
    const int row = blockIdx.x;
    const int tid = threadIdx.x;
    __shared__ float red[8];
    __shared__ float stats[2];

    const float* xr = x + (size_t)row * EMB;
    const int c = tid * 4;
    float4 v = *(const float4*)(xr + c);
    float s = v.x + v.y + v.z + v.w;
#pragma unroll
    for (int o = 16; o; o >>= 1) s += __shfl_xor_sync(0xffffffffu, s, o);
    if ((tid & 31) == 0) red[tid >> 5] = s;
    __syncthreads();
    if (tid == 0) {
        float t = 0.f;
#pragma unroll
        for (int i = 0; i < 8; i++) t += red[i];
        stats[0] = t * (1.f / EMB);
    }
    __syncthreads();
    const float mu = stats[0];

    float dx0 = v.x - mu, dx1 = v.y - mu, dx2 = v.z - mu, dx3 = v.w - mu;
    float sq = dx0 * dx0 + dx1 * dx1 + dx2 * dx2 + dx3 * dx3;
#pragma unroll
    for (int o = 16; o; o >>= 1) sq += __shfl_xor_sync(0xffffffffu, sq, o);
    if ((tid & 31) == 0) red[tid >> 5] = sq;
    __syncthreads();
    if (tid == 0) {
        float t = 0.f;
#pragma unroll
        for (int i = 0; i < 8; i++) t += red[i];
        stats[1] = rsqrtf(t * (1.f / EMB) + 1e-6f);
    }
    __syncthreads();
    const float r = stats[1];

    float4 g4 = *(const float4*)(gam + c);
    float4 b4 = *(const float4*)(bet + c);
    size_t off = (size_t)row * EMB + c;
    float4 hv = *(float4*)(h + off);
    hv.x += dx0 * r * g4.x + b4.x;
    hv.y += dx1 * r * g4.y + b4.y;
    hv.z += dx2 * r * g4.z + b4.z;
    hv.w += dx3 * r * g4.w + b4.w;
    *(float4*)(h + off) = hv;
    uint32_t h0, l0, h1, l1;
    split_pack(hv.x, hv.y, h0, l0);
    split_pack(hv.z, hv.w, h1, l1);
    *(uint32_t*)(ah + off) = h0; *(uint32_t*)(ah + off + 2) = h1;
    *(uint32_t*)(al + off) = l0; *(uint32_t*)(al + off + 2) = l1;
}

// ==================== host launch ====================
static void* sym_addr(const void* sym) {
    void* p = nullptr;
    cudaGetSymbolAddress(&p, sym);
    return p;
}

extern "C" void kernel_launch(void* const* d_in, const int* in_sizes, int n_in,
                              void* d_out, int out_size)
{
    const int*   x   = (const int*)d_in[0];
    const float* we  = (const float*)d_in[1];
    const float* pe  = (const float*)d_in[2];
    const float* KQV = (const float*)d_in[3];
    const float* WO  = (const float*)d_in[4];
    const float* Wup = (const float*)d_in[5];
    const float* bup = (const float*)d_in[6];
    const float* Wdn = (const float*)d_in[7];
    const float* bdn = (const float*)d_in[8];
    const float* g1  = (const float*)d_in[9];
    const float* b1  = (const float*)d_in[10];
    const float* g2  = (const float*)d_in[11];
    const float* b2  = (const float*)d_in[12];
    const float* ub  = (const float*)d_in[13];
    float* out = (float*)d_out;

    float* h    = (float*)sym_addr(g_h);
    float* tmp  = (float*)sym_addr(g_tmp);
    bf16* ahi  = (bf16*)sym_addr(g_ahi);
    bf16* alo  = (bf16*)sym_addr(g_alo);
    bf16* ffh  = (bf16*)sym_addr(g_ffh);
    bf16* ffl  = (bf16*)sym_addr(g_ffl);
    bf16* qkvh = (bf16*)sym_addr(g_qkvh);
    bf16* qkvl = (bf16*)sym_addr(g_qkvl);
    bf16* ath  = (bf16*)sym_addr(g_ath);
    bf16* atl  = (bf16*)sym_addr(g_atl);
    bf16* wkqv_h = (bf16*)sym_addr(g_wkqv_hi);
    bf16* wkqv_l = (bf16*)sym_addr(g_wkqv_lo);
    bf16* wo_h   = (bf16*)sym_addr(g_wo_hi);
    bf16* wo_l   = (bf16*)sym_addr(g_wo_lo);
    bf16* wup_h  = (bf16*)sym_addr(g_wup_hi);
    bf16* wup_l  = (bf16*)sym_addr(g_wup_lo);
    bf16* wdn_h  = (bf16*)sym_addr(g_wdn_hi);
    bf16* wdn_l  = (bf16*)sym_addr(g_wdn_lo);
    bf16* we_h   = (bf16*)sym_addr(g_we_hi);
    bf16* we_l   = (bf16*)sym_addr(g_we_lo);

    cudaFuncSetAttribute(hgemm_kernel<false, false, true>,
                         cudaFuncAttributeMaxDynamicSharedMemorySize, GEMM_SMEM);
    cudaFuncSetAttribute(hgemm_kernel<false, false, false>,
                         cudaFuncAttributeMaxDynamicSharedMemorySize, GEMM_SMEM);
    cudaFuncSetAttribute(hgemm_kernel<true, true, true>,
                         cudaFuncAttributeMaxDynamicSharedMemorySize, GEMM_SMEM);
    cudaFuncSetAttribute(hgemm_kernel<true, false, false>,
                         cudaFuncAttributeMaxDynamicSharedMemorySize, GEMM_SMEM);
    cudaFuncSetAttribute(flash_mma_kernel,
                         cudaFuncAttributeMaxDynamicSharedMemorySize, FA_SMEM);

    // ---- weight conversion (transpose to [N][K] + hi/lo split) ----
    dim3 tb(32, 8);
    for (int l = 0; l < NL; l++) {
        cvt_t_kernel<<<dim3(3 * EMB / 32, EMB / 32), tb>>>(
            KQV + (size_t)l * EMB * 3 * EMB,
            wkqv_h + (size_t)l * 3 * EMB * EMB, wkqv_l + (size_t)l * 3 * EMB * EMB,
            EMB, 3 * EMB);
        cvt_t_kernel<<<dim3(EMB / 32, EMB / 32), tb>>>(
            WO + (size_t)l * EMB * EMB,
            wo_h + (size_t)l * EMB * EMB, wo_l + (size_t)l * EMB * EMB,
            EMB, EMB);
        cvt_t_kernel<<<dim3(FF / 32, EMB / 32), tb>>>(
            Wup + (size_t)l * EMB * FF,
            wup_h + (size_t)l * (size_t)EMB * FF, wup_l + (size_t)l * (size_t)EMB * FF,
            EMB, FF);
        cvt_t_kernel<<<dim3(EMB / 32, FF / 32), tb>>>(
            Wdn + (size_t)l * FF * EMB,
            wdn_h + (size_t)l * (size_t)FF * EMB, wdn_l + (size_t)l * (size_t)FF * EMB,
            FF, EMB);
    }
    cvt_kernel<<<(unsigned)((size_t)VOC * EMB / 4 / 256), 256>>>(
        we, we_h, we_l, (size_t)VOC * EMB / 4);

    embed_kernel<<<BS, 256>>>(x, we, pe, h, ahi, alo);

    for (int l = 0; l < NL; l++) {
        // qkv(hi/lo) = h @ KQV[l]
        hgemm_kernel<false, false, true>
            <<<dim3(3 * EMB / GBN, BS / GBM), 256, GEMM_SMEM>>>(
                ahi, alo,
                wkqv_h + (size_t)l * 3 * EMB * EMB, wkqv_l + (size_t)l * 3 * EMB * EMB,
                nullptr, nullptr, qkvh, qkvl, BS, 3 * EMB, EMB);

        // attention -> attn(hi/lo)
        flash_mma_kernel<<<dim3(SEQ / 64, NH, BATCH), 128, FA_SMEM>>>(
            qkvh, qkvl, ath, atl);

        // tmp = attn @ WO[l]
        hgemm_kernel<false, false, false>
            <<<dim3(EMB / GBN, BS / GBM), 256, GEMM_SMEM>>>(
                ath, atl,
                wo_h + (size_t)l * EMB * EMB, wo_l + (size_t)l * EMB * EMB,
                nullptr, tmp, nullptr, nullptr, BS, EMB, EMB);

        // h += LN(tmp); h split -> ahi/alo
        ln_add_kernel<<<BS, 256>>>(tmp, g1 + l * EMB, b1 + l * EMB, h, ahi, alo);

        // ff(hi/lo) = relu(h @ W_up[l] + b_up[l])
        hgemm_kernel<true, true, true>
            <<<dim3(FF / GBN, BS / GBM), 256, GEMM_SMEM>>>(
                ahi, alo,
                wup_h + (size_t)l * (size_t)EMB * FF, wup_l + (size_t)l * (size_t)EMB * FF,
                bup + (size_t)l * FF, nullptr, ffh, ffl, BS, FF, EMB);

        // tmp = ff @ W_down[l] + b_down[l]
        hgemm_kernel<true, false, false>
            <<<dim3(EMB / GBN, BS / GBM), 256, GEMM_SMEM>>>(
                ffh, ffl,
                wdn_h + (size_t)l * (size_t)FF * EMB, wdn_l + (size_t)l * (size_t)FF * EMB,
                bdn + (size_t)l * EMB, tmp, nullptr, nullptr, BS, EMB, FF);

        // h += LN(tmp); h split -> ahi/alo
        ln_add_kernel<<<BS, 256>>>(tmp, g2 + l * EMB, b2 + l * EMB, h, ahi, alo);
    }

    // logits = h @ we^T + unembed_b
    hgemm_kernel<true, false, false>
        <<<dim3(VOC / GBN, BS / GBM), 256, GEMM_SMEM>>>(
            ahi, alo, we_h, we_l, ub, out, nullptr, nullptr, BS, VOC, EMB);
}

// round 17
// speedup vs baseline: 1.5851x; 1.5851x over previous
#include <cuda_runtime.h>
#include <cuda_bf16.h>
#include <cstdint>

// Problem constants
#define BATCH 2
#define SEQ   2048
#define EMB   1024
#define NH    16
#define HD    64
#define FF    4096
#define NL    4
#define VOC   32000
#define BS    (BATCH*SEQ)   // 4096 rows

typedef __nv_bfloat16 bf16;

// ---------------- scratch (device globals; no allocation) ----------------
__device__ float g_h   [(size_t)BS * EMB];
__device__ float g_tmp [(size_t)BS * EMB];

__device__ bf16 g_ahi [(size_t)BS * EMB];      // h split (gemm A input)
__device__ bf16 g_alo [(size_t)BS * EMB];
__device__ bf16 g_ffh [(size_t)BS * FF];       // FF hidden split
__device__ bf16 g_ffl [(size_t)BS * FF];
__device__ bf16 g_qkvh[(size_t)BS * 3 * EMB];  // qkv split
__device__ bf16 g_qkvl[(size_t)BS * 3 * EMB];
__device__ bf16 g_ath [(size_t)BS * EMB];      // attention out split
__device__ bf16 g_atl [(size_t)BS * EMB];

__device__ bf16 g_wkqv_hi[(size_t)NL * 3 * EMB * EMB];
__device__ bf16 g_wkqv_lo[(size_t)NL * 3 * EMB * EMB];
__device__ bf16 g_wo_hi  [(size_t)NL * EMB * EMB];
__device__ bf16 g_wo_lo  [(size_t)NL * EMB * EMB];
__device__ bf16 g_wup_hi [(size_t)NL * EMB * FF];
__device__ bf16 g_wup_lo [(size_t)NL * EMB * FF];
__device__ bf16 g_wdn_hi [(size_t)NL * FF * EMB];
__device__ bf16 g_wdn_lo [(size_t)NL * FF * EMB];
__device__ bf16 g_we_hi  [(size_t)VOC * EMB];
__device__ bf16 g_we_lo  [(size_t)VOC * EMB];

// ==================== PTX helpers (baseline ISA only) ====================
__device__ __forceinline__ uint32_t cvta_smem(const void* p) {
    uint32_t a;
    asm("{ .reg .u64 t; cvta.to.shared.u64 t, %1; cvt.u32.u64 %0, t; }"
        : "=r"(a) : "l"(p));
    return a;
}
__device__ __forceinline__ void cp_async16(uint32_t dst, const void* src) {
    asm volatile("cp.async.cg.shared.global [%0], [%1], 16;" :: "r"(dst), "l"(src));
}
__device__ __forceinline__ void cp_commit() {
    asm volatile("cp.async.commit_group;" ::: "memory");
}
__device__ __forceinline__ void cp_wait1() {
    asm volatile("cp.async.wait_group 1;" ::: "memory");
}
__device__ __forceinline__ void cp_wait0() {
    asm volatile("cp.async.wait_group 0;" ::: "memory");
}
__device__ __forceinline__ void ldmatrix_x4(uint32_t* r, uint32_t addr) {
    asm volatile("ldmatrix.sync.aligned.m8n8.x4.shared.b16 {%0,%1,%2,%3}, [%4];"
                 : "=r"(r[0]), "=r"(r[1]), "=r"(r[2]), "=r"(r[3]) : "r"(addr));
}
__device__ __forceinline__ void ldmatrix_x4_t(uint32_t* r, uint32_t addr) {
    asm volatile("ldmatrix.sync.aligned.m8n8.x4.trans.shared.b16 {%0,%1,%2,%3}, [%4];"
                 : "=r"(r[0]), "=r"(r[1]), "=r"(r[2]), "=r"(r[3]) : "r"(addr));
}
__device__ __forceinline__ void mma_bf16(float* c, const uint32_t* a, const uint32_t* b) {
    asm volatile(
        "mma.sync.aligned.m16n8k16.row.col.f32.bf16.bf16.f32 "
        "{%0,%1,%2,%3}, {%4,%5,%6,%7}, {%8,%9}, {%0,%1,%2,%3};"
        : "+f"(c[0]), "+f"(c[1]), "+f"(c[2]), "+f"(c[3])
        : "r"(a[0]), "r"(a[1]), "r"(a[2]), "r"(a[3]), "r"(b[0]), "r"(b[1]));
}
__device__ __forceinline__ void sts32(uint32_t addr, uint32_t v) {
    asm volatile("st.shared.b32 [%0], %1;" :: "r"(addr), "r"(v) : "memory");
}
__device__ __forceinline__ void split_pack(float a, float b, uint32_t& hi, uint32_t& lo) {
    bf16 ha = __float2bfloat16(a), hb = __float2bfloat16(b);
    bf16 la = __float2bfloat16(a - __bfloat162float(ha));
    bf16 lb = __float2bfloat16(b - __bfloat162float(hb));
    __nv_bfloat162 H; H.x = ha; H.y = hb;
    __nv_bfloat162 L; L.x = la; L.y = lb;
    hi = *(uint32_t*)&H; lo = *(uint32_t*)&L;
}

// ==================== weight conversion kernels ====================
__global__ void __launch_bounds__(256) cvt_kernel(
    const float* __restrict__ in, bf16* __restrict__ hi,
    bf16* __restrict__ lo, size_t n4)
{
    size_t i = (size_t)blockIdx.x * 256 + threadIdx.x;
    if (i >= n4) return;
    float4 v = ((const float4*)in)[i];
    uint32_t h0, l0, h1, l1;
    split_pack(v.x, v.y, h0, l0);
    split_pack(v.z, v.w, h1, l1);
    ((uint32_t*)hi)[2 * i]     = h0;
    ((uint32_t*)hi)[2 * i + 1] = h1;
    ((uint32_t*)lo)[2 * i]     = l0;
    ((uint32_t*)lo)[2 * i + 1] = l1;
}

// fp32 [R][C] -> bf16 hi/lo transposed [C][R]
__global__ void __launch_bounds__(256) cvt_t_kernel(
    const float* __restrict__ in, bf16* __restrict__ hi,
    bf16* __restrict__ lo, int R, int C)
{
    __shared__ float t[32][33];
    const int c0 = blockIdx.x * 32, r0 = blockIdx.y * 32;
    const int tx = threadIdx.x, ty = threadIdx.y;   // 32 x 8
#pragma unroll
    for (int j = 0; j < 32; j += 8)
        t[ty + j][tx] = in[(size_t)(r0 + ty + j) * C + c0 + tx];
    __syncthreads();
#pragma unroll
    for (int j = 0; j < 32; j += 8) {
        float a = t[tx][ty + j];
        bf16 h = __float2bfloat16(a);
        bf16 l = __float2bfloat16(a - __bfloat162float(h));
        size_t o = (size_t)(c0 + ty + j) * R + r0 + tx;
        hi[o] = h; lo[o] = l;
    }
}

// ==================== HMMA bf16 split-3 GEMM (R15-proven 128x64 tile) ====================
// C = A(MxK) @ B(NxK)^T. 8 warps (4M x 2N), warp tile 32x32. K-chunk 64.
// Stage (49152 B): Ahi[0,16K) Alo[16K,32K) Bhi[32K,40K) Blo[40K,48K)
#define GBM 128
#define GBN 64
#define GBK 64
#define STG 49152
#define GEMM_SMEM (2 * STG)

__device__ __forceinline__ void hgemm_prefetch(
    const bf16* Ahi, const bf16* Alo, const bf16* Bhi, const bf16* Blo,
    int K, int m0, int n0, int tid, int k0, uint32_t st)
{
    const int ar = tid >> 1;             // 0..127
    const int as0 = (tid & 1) * 4;       // 0 or 4 (16B slots)
    const int br = tid >> 2;             // 0..63
    const int bs0 = (tid & 3) * 2;       // 0,2,4,6
    const bf16* pAh = Ahi + (size_t)(m0 + ar) * K + k0;
    const bf16* pAl = Alo + (size_t)(m0 + ar) * K + k0;
#pragma unroll
    for (int j = 0; j < 4; j++) {
        int s = as0 + j;
        uint32_t dst = st + ar * 128 + ((s * 16) ^ ((ar & 7) << 4));
        cp_async16(dst,         pAh + s * 8);
        cp_async16(dst + 16384, pAl + s * 8);
    }
    const bf16* pBh = Bhi + (size_t)(n0 + br) * K + k0;
    const bf16* pBl = Blo + (size_t)(n0 + br) * K + k0;
#pragma unroll
    for (int j = 0; j < 2; j++) {
        int s = bs0 + j;
        uint32_t dst = st + 32768 + br * 128 + ((s * 16) ^ ((br & 7) << 4));
        cp_async16(dst,        pBh + s * 8);
        cp_async16(dst + 8192, pBl + s * 8);
    }
}

template<bool BIAS, bool RELU, bool OUTBF>
__global__ void __launch_bounds__(256, 2) hgemm_kernel(
    const bf16* __restrict__ Ahi, const bf16* __restrict__ Alo,
    const bf16* __restrict__ Bhi, const bf16* __restrict__ Blo,
    const float* __restrict__ bias, float* __restrict__ C,
    bf16* __restrict__ Chi, bf16* __restrict__ Clo,
    int M, int N, int K)
{
    extern __shared__ char sm[];
    const int tid = threadIdx.x;
    const int lane = tid & 31;
    const int warp = tid >> 5;
    const int warpM = warp & 3;
    const int warpN = warp >> 2;
    const int m0 = blockIdx.y * GBM;
    const int n0 = blockIdx.x * GBN;
    const uint32_t sbase = cvta_smem(sm);

    float acc[2][4][4];
#pragma unroll
    for (int i = 0; i < 2; i++)
#pragma unroll
        for (int j = 0; j < 4; j++)
#pragma unroll
            for (int k = 0; k < 4; k++) acc[i][j][k] = 0.f;

    const int nch = K / GBK;

    hgemm_prefetch(Ahi, Alo, Bhi, Blo, K, m0, n0, tid, 0, sbase);
    cp_commit();

    const int a_row_b = warpM * 32 + (lane & 7) + ((lane >> 3) & 1) * 8;
    const int a_col_b = ((lane >> 4) & 1) * 16;
    const int b_row_b = warpN * 32 + (lane & 7) + ((lane >> 4) & 1) * 8;
    const int b_col_b = ((lane >> 3) & 1) * 16;

    for (int i = 0; i < nch; i++) {
        const int s = i & 1;
        if (i + 1 < nch) {
            hgemm_prefetch(Ahi, Alo, Bhi, Blo, K, m0, n0, tid,
                           (i + 1) * GBK, sbase + (s ^ 1) * STG);
            cp_commit();
            cp_wait1();
        } else {
            cp_wait0();
        }
        __syncthreads();

        const uint32_t st = sbase + s * STG;
#pragma unroll
        for (int kk = 0; kk < 4; kk++) {
            uint32_t ah[2][4], al[2][4];
#pragma unroll
            for (int mt = 0; mt < 2; mt++) {
                int row = a_row_b + mt * 16;
                int col = kk * 32 + a_col_b;
                uint32_t addr = st + row * 128 + (col ^ ((row & 7) << 4));
                ldmatrix_x4(ah[mt], addr);
                ldmatrix_x4(al[mt], addr + 16384);
            }
            uint32_t bh[4][2], bl[4][2];
#pragma unroll
            for (int nt2 = 0; nt2 < 2; nt2++) {
                int row = b_row_b + nt2 * 16;
                int col = kk * 32 + b_col_b;
                uint32_t addr = st + 32768 + row * 128 + (col ^ ((row & 7) << 4));
                uint32_t r[4];
                ldmatrix_x4(r, addr);
                bh[nt2 * 2][0] = r[0]; bh[nt2 * 2][1] = r[1];
                bh[nt2 * 2 + 1][0] = r[2]; bh[nt2 * 2 + 1][1] = r[3];
                ldmatrix_x4(r, addr + 8192);
                bl[nt2 * 2][0] = r[0]; bl[nt2 * 2][1] = r[1];
                bl[nt2 * 2 + 1][0] = r[2]; bl[nt2 * 2 + 1][1] = r[3];
            }
#pragma unroll
            for (int mt = 0; mt < 2; mt++)
#pragma unroll
                for (int nt = 0; nt < 4; nt++) mma_bf16(acc[mt][nt], ah[mt], bh[nt]);
#pragma unroll
            for (int mt = 0; mt < 2; mt++)
#pragma unroll
                for (int nt = 0; nt < 4; nt++) mma_bf16(acc[mt][nt], ah[mt], bl[nt]);
#pragma unroll
            for (int mt = 0; mt < 2; mt++)
#pragma unroll
                for (int nt = 0; nt < 4; nt++) mma_bf16(acc[mt][nt], al[mt], bh[nt]);
        }
        __syncthreads();
    }

    // ---- epilogue ----
    const int er = lane >> 2;
    const int ec = (lane & 3) * 2;
#pragma unroll
    for (int mt = 0; mt < 2; mt++) {
#pragma unroll
        for (int nt = 0; nt < 4; nt++) {
            int col = n0 + warpN * 32 + nt * 8 + ec;
            float bx = 0.f, by = 0.f;
            if (BIAS) { bx = bias[col]; by = bias[col + 1]; }
            int row0 = m0 + warpM * 32 + mt * 16 + er;
            float2 v0 = { acc[mt][nt][0] + bx, acc[mt][nt][1] + by };
            float2 v1 = { acc[mt][nt][2] + bx, acc[mt][nt][3] + by };
            if (RELU) {
                v0.x = fmaxf(v0.x, 0.f); v0.y = fmaxf(v0.y, 0.f);
                v1.x = fmaxf(v1.x, 0.f); v1.y = fmaxf(v1.y, 0.f);
            }
            if (OUTBF) {
                uint32_t h0, l0, h1, l1;
                split_pack(v0.x, v0.y, h0, l0);
                split_pack(v1.x, v1.y, h1, l1);
                size_t o0 = (size_t)row0 * N + col;
                size_t o1 = (size_t)(row0 + 8) * N + col;
                *(uint32_t*)(Chi + o0) = h0; *(uint32_t*)(Clo + o0) = l0;
                *(uint32_t*)(Chi + o1) = h1; *(uint32_t*)(Clo + o1) = l1;
            } else {
                *(float2*)(C + (size_t)row0 * N + col)       = v0;
                *(float2*)(C + (size_t)(row0 + 8) * N + col) = v1;
            }
        }
    }
}

// ==================== tensor-core flash attention (R15-proven core) ====================
#define FA_SMEM 98304

__global__ void __launch_bounds__(128, 2) flash_mma_kernel(
    const bf16* __restrict__ qh_g, const bf16* __restrict__ ql_g,
    bf16* __restrict__ oh_g, bf16* __restrict__ ol_g)
{
    extern __shared__ char sm[];
    const uint32_t sb = cvta_smem(sm);
    const int tid = threadIdx.x;
    const int lane = tid & 31;
    const int w = tid >> 5;
    const int qt = gridDim.x - 1 - blockIdx.x;   // longest first
    const int h = blockIdx.y;
    const int b = blockIdx.z;

    const uint32_t QH = sb, QL = sb + 8192;
    const uint32_t ST0 = sb + 16384;              // stage stride 32768
    const uint32_t PH = sb + 81920;               // PL = PH + 8192

    const size_t rowbase = (size_t)b * SEQ * (3 * EMB);
    const int hoff = h * (3 * HD);

    // ---- Q tile load (hi/lo) ----
    {
        const int r = tid >> 1;
        const int s0 = (tid & 1) * 4;
        const bf16* srcH = qh_g + rowbase + (size_t)(qt * 64 + r) * (3 * EMB) + hoff + HD;
        const bf16* srcL = ql_g + rowbase + (size_t)(qt * 64 + r) * (3 * EMB) + hoff + HD;
#pragma unroll
        for (int j = 0; j < 4; j++) {
            uint32_t o = r * 128 + (((s0 + j) * 16) ^ ((r & 7) << 4));
            cp_async16(QH + o, srcH + (s0 + j) * 8);
            cp_async16(QL + o, srcL + (s0 + j) * 8);
        }
    }
    cp_commit();

    const int pr = tid >> 1;
    const int ps0 = (tid & 1) * 4;
    const uint32_t prow = pr * 128;

#define PREFETCH_KV(kt_, stg_) do {                                              \
    const bf16* bH = qh_g + rowbase + (size_t)((kt_) * 64 + pr) * (3 * EMB) + hoff; \
    const bf16* bL = ql_g + rowbase + (size_t)((kt_) * 64 + pr) * (3 * EMB) + hoff; \
    _Pragma("unroll")                                                            \
    for (int j = 0; j < 4; j++) {                                                \
        uint32_t o = prow + (((ps0 + j) * 16) ^ ((pr & 7) << 4));                \
        cp_async16((stg_) + o,         bH + (ps0 + j) * 8);                      \
        cp_async16((stg_) + 8192 + o,  bL + (ps0 + j) * 8);                      \
        cp_async16((stg_) + 16384 + o, bH + 128 + (ps0 + j) * 8);                \
        cp_async16((stg_) + 24576 + o, bL + 128 + (ps0 + j) * 8);                \
    } } while (0)

    PREFETCH_KV(0, ST0);
    cp_commit();

    const int row_a = w * 16 + (lane & 15);
    const uint32_t colg_a = ((lane >> 4) & 1) * 16;
    const int row_kb = (lane & 7) + ((lane >> 4) & 1) * 8;
    const uint32_t col_kb = ((lane >> 3) & 1) * 16;
    const int row_v = (lane & 7) + ((lane >> 3) & 1) * 8;
    const uint32_t col_v = ((lane >> 4) & 1) * 16;

    const int er = lane >> 2, ec = (lane & 3) * 2;
    const int q0 = qt * 64 + w * 16 + er;

    float o_[8][4];
#pragma unroll
    for (int i = 0; i < 8; i++)
#pragma unroll
        for (int j = 0; j < 4; j++) o_[i][j] = 0.f;
    float m0 = -1e30f, m1 = -1e30f, l0 = 0.f, l1 = 0.f;

    const int nkt = qt + 1;
    for (int kt = 0; kt < nkt; kt++) {
        const uint32_t stg = ST0 + (kt & 1) * 32768;
        if (kt + 1 < nkt) {
            PREFETCH_KV(kt + 1, ST0 + ((kt + 1) & 1) * 32768);
            cp_commit();
            cp_wait1();
        } else {
            cp_wait0();
        }
        __syncthreads();

        float sa[8][4];
#pragma unroll
        for (int i = 0; i < 8; i++)
#pragma unroll
            for (int j = 0; j < 4; j++) sa[i][j] = 0.f;
#pragma unroll
        for (int kk = 0; kk < 4; kk++) {
            uint32_t aaddr = QH + row_a * 128 + ((kk * 32 + colg_a) ^ ((row_a & 7) << 4));
            uint32_t qh[4], ql[4];
            ldmatrix_x4(qh, aaddr);
            ldmatrix_x4(ql, aaddr + 8192);
#pragma unroll
            for (int ntp = 0; ntp < 4; ntp++) {
                int rb = ntp * 16 + row_kb;
                uint32_t baddr = stg + rb * 128 + ((kk * 32 + col_kb) ^ ((rb & 7) << 4));
                uint32_t kh[4], kl[4];
                ldmatrix_x4(kh, baddr);
                ldmatrix_x4(kl, baddr + 8192);
                mma_bf16(sa[2 * ntp],     qh, kh);
                mma_bf16(sa[2 * ntp + 1], qh, kh + 2);
                mma_bf16(sa[2 * ntp],     qh, kl);
                mma_bf16(sa[2 * ntp + 1], qh, kl + 2);
                mma_bf16(sa[2 * ntp],     ql, kh);
                mma_bf16(sa[2 * ntp + 1], ql, kh + 2);
            }
        }

        const bool diag = (kt == qt);
        float rm0 = -1e30f, rm1 = -1e30f;
#pragma unroll
        for (int nt = 0; nt < 8; nt++) {
#pragma unroll
            for (int c = 0; c < 4; c++) sa[nt][c] *= 0.125f;
            if (diag) {
                int kc = kt * 64 + nt * 8 + ec;
                if (kc     > q0)     sa[nt][0] = -1e30f;
                if (kc + 1 > q0)     sa[nt][1] = -1e30f;
                if (kc     > q0 + 8) sa[nt][2] = -1e30f;
                if (kc + 1 > q0 + 8) sa[nt][3] = -1e30f;
            }
            rm0 = fmaxf(rm0, fmaxf(sa[nt][0], sa[nt][1]));
            rm1 = fmaxf(rm1, fmaxf(sa[nt][2], sa[nt][3]));
        }
        rm0 = fmaxf(rm0, __shfl_xor_sync(0xffffffffu, rm0, 1));
        rm0 = fmaxf(rm0, __shfl_xor_sync(0xffffffffu, rm0, 2));
        rm1 = fmaxf(rm1, __shfl_xor_sync(0xffffffffu, rm1, 1));
        rm1 = fmaxf(rm1, __shfl_xor_sync(0xffffffffu, rm1, 2));
        const float mn0 = fmaxf(m0, rm0), mn1 = fmaxf(m1, rm1);
        const float cr0 = __expf(m0 - mn0), cr1 = __expf(m1 - mn1);
        m0 = mn0; m1 = mn1;
        float sum0 = 0.f, sum1 = 0.f;
        const int rA = w * 16 + er;
        const uint32_t rAoff = rA * 128, rBoff = (rA + 8) * 128;
        const uint32_t xsw = (uint32_t)((rA & 7) << 4);
#pragma unroll
        for (int nt = 0; nt < 8; nt++) {
            float p0 = __expf(sa[nt][0] - mn0);
            float p1 = __expf(sa[nt][1] - mn0);
            float p2 = __expf(sa[nt][2] - mn1);
            float p3 = __expf(sa[nt][3] - mn1);
            sum0 += p0 + p1; sum1 += p2 + p3;
            uint32_t hA, lA, hB, lB;
            split_pack(p0, p1, hA, lA);
            split_pack(p2, p3, hB, lB);
            uint32_t cb = (uint32_t)(nt * 16 + ec * 2) ^ xsw;
            sts32(PH + rAoff + cb, hA);
            sts32(PH + 8192 + rAoff + cb, lA);
            sts32(PH + rBoff + cb, hB);
            sts32(PH + 8192 + rBoff + cb, lB);
        }
        sum0 += __shfl_xor_sync(0xffffffffu, sum0, 1);
        sum0 += __shfl_xor_sync(0xffffffffu, sum0, 2);
        sum1 += __shfl_xor_sync(0xffffffffu, sum1, 1);
        sum1 += __shfl_xor_sync(0xffffffffu, sum1, 2);
        l0 = l0 * cr0 + sum0;
        l1 = l1 * cr1 + sum1;
#pragma unroll
        for (int nt = 0; nt < 8; nt++) {
            o_[nt][0] *= cr0; o_[nt][1] *= cr0;
            o_[nt][2] *= cr1; o_[nt][3] *= cr1;
        }
        __syncwarp();

#pragma unroll
        for (int kk2 = 0; kk2 < 4; kk2++) {
            uint32_t paddr = PH + row_a * 128 + ((kk2 * 32 + colg_a) ^ ((row_a & 7) << 4));
            uint32_t ph[4], pl[4];
            ldmatrix_x4(ph, paddr);
            ldmatrix_x4(pl, paddr + 8192);
#pragma unroll
            for (int ntp = 0; ntp < 4; ntp++) {
                int rv = kk2 * 16 + row_v;
                uint32_t vaddr = stg + 16384 + rv * 128 + ((ntp * 32 + col_v) ^ ((rv & 7) << 4));
                uint32_t vh[4], vl[4];
                ldmatrix_x4_t(vh, vaddr);
                ldmatrix_x4_t(vl, vaddr + 8192);
                mma_bf16(o_[2 * ntp],     ph, vh);
                mma_bf16(o_[2 * ntp + 1], ph, vh + 2);
                mma_bf16(o_[2 * ntp],     ph, vl);
                mma_bf16(o_[2 * ntp + 1], ph, vl + 2);
                mma_bf16(o_[2 * ntp],     pl, vh);
                mma_bf16(o_[2 * ntp + 1], pl, vh + 2);
            }
        }
        __syncthreads();
    }

    // ---- epilogue: write hi/lo bf16 split of O ----
    const float i0 = 1.f / l0, i1 = 1.f / l1;
    const size_t base0 = (size_t)(b * SEQ + q0) * EMB + h * HD;
    const size_t base1 = base0 + (size_t)8 * EMB;
#pragma unroll
    for (int nt = 0; nt < 8; nt++) {
        uint32_t h0, l0v, h1, l1v;
        split_pack(o_[nt][0] * i0, o_[nt][1] * i0, h0, l0v);
        split_pack(o_[nt][2] * i1, o_[nt][3] * i1, h1, l1v);
        *(uint32_t*)(oh_g + base0 + nt * 8 + ec) = h0;
        *(uint32_t*)(ol_g + base0 + nt * 8 + ec) = l0v;
        *(uint32_t*)(oh_g + base1 + nt * 8 + ec) = h1;
        *(uint32_t*)(ol_g + base1 + nt * 8 + ec) = l1v;
    }
#undef PREFETCH_KV
}

// ==================== embed (writes fp32 h + hi/lo split) ====================
__global__ void __launch_bounds__(256) embed_kernel(
    const int* __restrict__ x, const float* __restrict__ we,
    const float* __restrict__ pe, float* __restrict__ h,
    bf16* __restrict__ ah, bf16* __restrict__ al)
{
    int row = blockIdx.x;
    int s   = row % SEQ;
    int tok = x[row];
    int c = threadIdx.x * 4;
    float4 a = *(const float4*)(we + (size_t)tok * EMB + c);
    float4 b = *(const float4*)(pe + (size_t)s   * EMB + c);
    float4 o; o.x = a.x + b.x; o.y = a.y + b.y; o.z = a.z + b.z; o.w = a.w + b.w;
    size_t off = (size_t)row * EMB + c;
    *(float4*)(h + off) = o;
    uint32_t h0, l0, h1, l1;
    split_pack(o.x, o.y, h0, l0);
    split_pack(o.z, o.w, h1, l1);
    *(uint32_t*)(ah + off) = h0; *(uint32_t*)(ah + off + 2) = h1;
    *(uint32_t*)(al + off) = l0; *(uint32_t*)(al + off + 2) = l1;
}

// ==================== fused LayerNorm + residual (+ hi/lo split out) ====================
__global__ void __launch_bounds__(256) ln_add_kernel(
    const float* __restrict__ x, const float* __restrict__ gam,
    const float* __restrict__ bet, float* __restrict__ h,
    bf16* __restrict__ ah, bf16* __restrict__ al)
{
    const int row = blockIdx.x;
    const int tid = threadIdx.x;
    __shared__ float red[8];
    __shared__ float stats[2];

    const float* xr = x + (size_t)row * EMB;
    const int c = tid * 4;
    float4 v = *(const float4*)(xr + c);
    float s = v.x + v.y + v.z + v.w;
#pragma unroll
    for (int o = 16; o; o >>= 1) s += __shfl_xor_sync(0xffffffffu, s, o);
    if ((tid & 31) == 0) red[tid >> 5] = s;
    __syncthreads();
    if (tid == 0) {
        float t = 0.f;
#pragma unroll
        for (int i = 0; i < 8; i++) t += red[i];
        stats[0] = t * (1.f / EMB);
    }
    __syncthreads();
    const float mu = stats[0];

    float dx0 = v.x - mu, dx1 = v.y - mu, dx2 = v.z - mu, dx3 = v.w - mu;
    float sq = dx0 * dx0 + dx1 * dx1 + dx2 * dx2 + dx3 * dx3;
#pragma unroll
    for (int o = 16; o; o >>= 1) sq += __shfl_xor_sync(0xffffffffu, sq, o);
    if ((tid & 31) == 0) red[tid >> 5] = sq;
    __syncthreads();
    if (tid == 0) {
        float t = 0.f;
#pragma unroll
        for (int i = 0; i < 8; i++) t += red[i];
        stats[1] = rsqrtf(t * (1.f / EMB) + 1e-6f);
    }
    __syncthreads();
    const float r = stats[1];

    float4 g4 = *(const float4*)(gam + c);
    float4 b4 = *(const float4*)(bet + c);
    size_t off = (size_t)row * EMB + c;
    float4 hv = *(float4*)(h + off);
    hv.x += dx0 * r * g4.x + b4.x;
    hv.y += dx1 * r * g4.y + b4.y;
    hv.z += dx2 * r * g4.z + b4.z;
    hv.w += dx3 * r * g4.w + b4.w;
    *(float4*)(h + off) = hv;
    uint32_t h0, l0, h1, l1;
    split_pack(hv.x, hv.y, h0, l0);
    split_pack(hv.z, hv.w, h1, l1);
    *(uint32_t*)(ah + off) = h0; *(uint32_t*)(ah + off + 2) = h1;
    *(uint32_t*)(al + off) = l0; *(uint32_t*)(al + off + 2) = l1;
}

// ==================== host launch ====================
static void* sym_addr(const void* sym) {
    void* p = nullptr;
    cudaGetSymbolAddress(&p, sym);
    return p;
}

extern "C" void kernel_launch(void* const* d_in, const int* in_sizes, int n_in,
                              void* d_out, int out_size)
{
    const int*   x   = (const int*)d_in[0];
    const float* we  = (const float*)d_in[1];
    const float* pe  = (const float*)d_in[2];
    const float* KQV = (const float*)d_in[3];
    const float* WO  = (const float*)d_in[4];
    const float* Wup = (const float*)d_in[5];
    const float* bup = (const float*)d_in[6];
    const float* Wdn = (const float*)d_in[7];
    const float* bdn = (const float*)d_in[8];
    const float* g1  = (const float*)d_in[9];
    const float* b1  = (const float*)d_in[10];
    const float* g2  = (const float*)d_in[11];
    const float* b2  = (const float*)d_in[12];
    const float* ub  = (const float*)d_in[13];
    float* out = (float*)d_out;

    float* h    = (float*)sym_addr(g_h);
    float* tmp  = (float*)sym_addr(g_tmp);
    bf16* ahi  = (bf16*)sym_addr(g_ahi);
    bf16* alo  = (bf16*)sym_addr(g_alo);
    bf16* ffh  = (bf16*)sym_addr(g_ffh);
    bf16* ffl  = (bf16*)sym_addr(g_ffl);
    bf16* qkvh = (bf16*)sym_addr(g_qkvh);
    bf16* qkvl = (bf16*)sym_addr(g_qkvl);
    bf16* ath  = (bf16*)sym_addr(g_ath);
    bf16* atl  = (bf16*)sym_addr(g_atl);
    bf16* wkqv_h = (bf16*)sym_addr(g_wkqv_hi);
    bf16* wkqv_l = (bf16*)sym_addr(g_wkqv_lo);
    bf16* wo_h   = (bf16*)sym_addr(g_wo_hi);
    bf16* wo_l   = (bf16*)sym_addr(g_wo_lo);
    bf16* wup_h  = (bf16*)sym_addr(g_wup_hi);
    bf16* wup_l  = (bf16*)sym_addr(g_wup_lo);
    bf16* wdn_h  = (bf16*)sym_addr(g_wdn_hi);
    bf16* wdn_l  = (bf16*)sym_addr(g_wdn_lo);
    bf16* we_h   = (bf16*)sym_addr(g_we_hi);
    bf16* we_l   = (bf16*)sym_addr(g_we_lo);

    cudaFuncSetAttribute(hgemm_kernel<false, false, true>,
                         cudaFuncAttributeMaxDynamicSharedMemorySize, GEMM_SMEM);
    cudaFuncSetAttribute(hgemm_kernel<false, false, false>,
                         cudaFuncAttributeMaxDynamicSharedMemorySize, GEMM_SMEM);
    cudaFuncSetAttribute(hgemm_kernel<true, true, true>,
                         cudaFuncAttributeMaxDynamicSharedMemorySize, GEMM_SMEM);
    cudaFuncSetAttribute(hgemm_kernel<true, false, false>,
                         cudaFuncAttributeMaxDynamicSharedMemorySize, GEMM_SMEM);
    cudaFuncSetAttribute(flash_mma_kernel,
                         cudaFuncAttributeMaxDynamicSharedMemorySize, FA_SMEM);

    // ---- weight conversion (transpose to [N][K] + hi/lo split) ----
    dim3 tb(32, 8);
    for (int l = 0; l < NL; l++) {
        cvt_t_kernel<<<dim3(3 * EMB / 32, EMB / 32), tb>>>(
            KQV + (size_t)l * EMB * 3 * EMB,
            wkqv_h + (size_t)l * 3 * EMB * EMB, wkqv_l + (size_t)l * 3 * EMB * EMB,
            EMB, 3 * EMB);
        cvt_t_kernel<<<dim3(EMB / 32, EMB / 32), tb>>>(
            WO + (size_t)l * EMB * EMB,
            wo_h + (size_t)l * EMB * EMB, wo_l + (size_t)l * EMB * EMB,
            EMB, EMB);
        cvt_t_kernel<<<dim3(FF / 32, EMB / 32), tb>>>(
            Wup + (size_t)l * EMB * FF,
            wup_h + (size_t)l * (size_t)EMB * FF, wup_l + (size_t)l * (size_t)EMB * FF,
            EMB, FF);
        cvt_t_kernel<<<dim3(EMB / 32, FF / 32), tb>>>(
            Wdn + (size_t)l * FF * EMB,
            wdn_h + (size_t)l * (size_t)FF * EMB, wdn_l + (size_t)l * (size_t)FF * EMB,
            FF, EMB);
    }
    cvt_kernel<<<(unsigned)((size_t)VOC * EMB / 4 / 256), 256>>>(
        we, we_h, we_l, (size_t)VOC * EMB / 4);

    embed_kernel<<<BS, 256>>>(x, we, pe, h, ahi, alo);

    for (int l = 0; l < NL; l++) {
        // qkv(hi/lo) = h @ KQV[l]
        hgemm_kernel<false, false, true>
            <<<dim3(3 * EMB / GBN, BS / GBM), 256, GEMM_SMEM>>>(
                ahi, alo,
                wkqv_h + (size_t)l * 3 * EMB * EMB, wkqv_l + (size_t)l * 3 * EMB * EMB,
                nullptr, nullptr, qkvh, qkvl, BS, 3 * EMB, EMB);

        // attention -> attn(hi/lo)
        flash_mma_kernel<<<dim3(SEQ / 64, NH, BATCH), 128, FA_SMEM>>>(
            qkvh, qkvl, ath, atl);

        // tmp = attn @ WO[l]
        hgemm_kernel<false, false, false>
            <<<dim3(EMB / GBN, BS / GBM), 256, GEMM_SMEM>>>(
                ath, atl,
                wo_h + (size_t)l * EMB * EMB, wo_l + (size_t)l * EMB * EMB,
                nullptr, tmp, nullptr, nullptr, BS, EMB, EMB);

        // h += LN(tmp); h split -> ahi/alo
        ln_add_kernel<<<BS, 256>>>(tmp, g1 + l * EMB, b1 + l * EMB, h, ahi, alo);

        // ff(hi/lo) = relu(h @ W_up[l] + b_up[l])
        hgemm_kernel<true, true, true>
            <<<dim3(FF / GBN, BS / GBM), 256, GEMM_SMEM>>>(
                ahi, alo,
                wup_h + (size_t)l * (size_t)EMB * FF, wup_l + (size_t)l * (size_t)EMB * FF,
                bup + (size_t)l * FF, nullptr, ffh, ffl, BS, FF, EMB);

        // tmp = ff @ W_down[l] + b_down[l]
        hgemm_kernel<true, false, false>
            <<<dim3(EMB / GBN, BS / GBM), 256, GEMM_SMEM>>>(
                ffh, ffl,
                wdn_h + (size_t)l * (size_t)FF * EMB, wdn_l + (size_t)l * (size_t)FF * EMB,
                bdn + (size_t)l * EMB, tmp, nullptr, nullptr, BS, EMB, FF);

        // h += LN(tmp); h split -> ahi/alo
        ln_add_kernel<<<BS, 256>>>(tmp, g2 + l * EMB, b2 + l * EMB, h, ahi, alo);
    }

    // logits = h @ we^T + unembed_b
    hgemm_kernel<true, false, false>
        <<<dim3(VOC / GBN, BS / GBM), 256, GEMM_SMEM>>>(
            ahi, alo, we_h, we_l, ub, out, nullptr, nullptr, BS, VOC, EMB);
}